// round 3
// baseline (speedup 1.0000x reference)
#include <cuda_runtime.h>
#include <math.h>

#define HDIM 256
#define WDIM 256
#define WF   129
#define BSZ  4
#define CSZ  128
#define NBLK 8

// scratch spectrum buffer, layout [b, c, wf, h] as float2 (~135 MB)
__device__ float2 g_buf[(size_t)BSZ * CSZ * WF * HDIM];

__device__ __forceinline__ float2 cadd(float2 a, float2 b){ return make_float2(a.x+b.x, a.y+b.y); }
__device__ __forceinline__ float2 csub(float2 a, float2 b){ return make_float2(a.x-b.x, a.y-b.y); }
__device__ __forceinline__ float2 cmul(float2 a, float2 b){
    return make_float2(a.x*b.x - a.y*b.y, a.x*b.y + a.y*b.x);
}
__device__ __forceinline__ float2 cmulc(float2 a, float2 b){  // a * conj(b)
    return make_float2(a.x*b.x + a.y*b.y, a.y*b.x - a.x*b.y);
}

// packed f32x2 helpers (FFMA2: 2 fp32 FMAs per issue slot)
__device__ __forceinline__ double pk(float lo, float hi){
    double d; asm("mov.b64 %0, {%1, %2};" : "=d"(d) : "f"(lo), "f"(hi)); return d;
}
__device__ __forceinline__ void upk(double d, float& lo, float& hi){
    asm("mov.b64 {%0, %1}, %2;" : "=f"(lo), "=f"(hi) : "d"(d));
}
__device__ __forceinline__ double ffma2(double a, double b, double c){
    double r; asm("fma.rn.f32x2 %0, %1, %2, %3;" : "=d"(r) : "d"(a), "d"(b), "d"(c));
    return r;
}

// multiply by (-i) forward, (+i) inverse
template<bool INV>
__device__ __forceinline__ float2 mul_i(float2 a){
    return INV ? make_float2(-a.y, a.x) : make_float2(a.y, -a.x);
}

template<bool INV>
__device__ __forceinline__ void bf4(float2& x0, float2& x1, float2& x2, float2& x3){
    float2 t0 = cadd(x0, x2), t1 = csub(x0, x2);
    float2 t2 = cadd(x1, x3), t3 = csub(x1, x3);
    float2 j3 = mul_i<INV>(t3);
    x0 = cadd(t0, t2);
    x2 = csub(t0, t2);
    x1 = cadd(t1, j3);
    x3 = csub(t1, j3);
}

// In-register 16-point DFT (radix-4 x radix-4). Input v[n] natural order.
// Output: bin k = c + 4d lands in slot 4c + d  (slot(k) = ((k&3)<<2)|(k>>2)).
template<bool INV>
__device__ __forceinline__ void dft16(float2 v[16]){
    const float S = INV ? 1.f : -1.f;
    const float2 W1 = make_float2( 0.92387953251128674f, S*0.38268343236508978f);
    const float2 W2 = make_float2( 0.70710678118654752f, S*0.70710678118654752f);
    const float2 W3 = make_float2( 0.38268343236508978f, S*0.92387953251128674f);
    const float2 W6 = make_float2(-0.70710678118654752f, S*0.70710678118654752f);
    const float2 W9 = make_float2(-0.92387953251128674f, -S*0.38268343236508978f);

    bf4<INV>(v[0], v[4], v[8],  v[12]);
    bf4<INV>(v[1], v[5], v[9],  v[13]);
    bf4<INV>(v[2], v[6], v[10], v[14]);
    bf4<INV>(v[3], v[7], v[11], v[15]);
    v[5]  = cmul(v[5],  W1);
    v[9]  = cmul(v[9],  W2);
    v[13] = cmul(v[13], W3);
    v[6]  = cmul(v[6],  W2);
    v[10] = mul_i<INV>(v[10]);           // W16^4 = -/+ i
    v[14] = cmul(v[14], W6);
    v[7]  = cmul(v[7],  W3);
    v[11] = cmul(v[11], W6);
    v[15] = cmul(v[15], W9);
    bf4<INV>(v[0],  v[1],  v[2],  v[3]);
    bf4<INV>(v[4],  v[5],  v[6],  v[7]);
    bf4<INV>(v[8],  v[9],  v[10], v[11]);
    bf4<INV>(v[12], v[13], v[14], v[15]);
}

#define SLOT(k) ((((k) & 3) << 2) | ((k) >> 2))

__device__ __forceinline__ void build_tw(float2* tw, int tid){
    float s, c;
    sincosf((float)tid * (-6.283185307179586f / 256.f), &s, &c);
    tw[tid] = make_float2(c, s);
}

// ---------------------------------------------------------------------------
// K1: row rfft. CTA = 32 rows of one (b,c) image, packed 2 real rows / complex
// FFT (16 FFTs, 16 threads each). Output transposed [b,c,wf,h], scaled 1/256.
// ---------------------------------------------------------------------------
__global__ void __launch_bounds__(256) k_rowfft(const float* __restrict__ x){
    extern __shared__ char smraw[];
    float2* sbuf = (float2*)smraw;                 // 4352 float2 (T:272/fft, S:257/fft)
    float2* tw   = (float2*)(smraw + 34816);       // 256 float2

    const int tid = threadIdx.x;
    const int f = tid >> 4, t = tid & 15;
    const int bc = blockIdx.x >> 3;
    const int h0 = (blockIdx.x & 7) << 5;

    build_tw(tw, tid);

    const float* r0 = x + ((size_t)bc * HDIM + h0 + 2 * f) * WDIM;
    float2 v[16];
#pragma unroll
    for (int n1 = 0; n1 < 16; n1++)
        v[n1] = make_float2(r0[16 * n1 + t], r0[WDIM + 16 * n1 + t]);
    dft16<false>(v);
    __syncthreads();                               // tw ready

#pragma unroll
    for (int k1 = 0; k1 < 16; k1++){
        float2 bv = v[SLOT(k1)];
        if (k1) bv = cmul(bv, tw[t * k1]);
        sbuf[f * 272 + k1 * 17 + t] = bv;
    }
    __syncthreads();
#pragma unroll
    for (int n2 = 0; n2 < 16; n2++)
        v[n2] = sbuf[f * 272 + t * 17 + n2];
    __syncthreads();                               // T reads done before S writes
    dft16<false>(v);
#pragma unroll
    for (int k2 = 0; k2 < 16; k2++)
        sbuf[f * 257 + t + 16 * k2] = v[SLOT(k2)];
    __syncthreads();

    float2* dst = g_buf + (size_t)bc * WF * HDIM;
    for (int e = tid; e < WF * 32; e += 256){
        const int wf = e >> 5, r = e & 31, fp = r >> 1;
        float2 Z1 = sbuf[fp * 257 + wf];
        float2 Z2 = sbuf[fp * 257 + ((256 - wf) & 255)];
        float2 val = (r & 1)
            ? make_float2((Z1.y + Z2.y) * 0.5f, (Z2.x - Z1.x) * 0.5f)
            : make_float2((Z1.x + Z2.x) * 0.5f, (Z1.y - Z2.y) * 0.5f);
        dst[(size_t)wf * HDIM + h0 + r] =
            make_float2(val.x * (1.f / 256.f), val.y * (1.f / 256.f));
    }
}

// ---------------------------------------------------------------------------
// K2: column FFT over h (16 channels of one block), per-bin block MLP with
// packed f32x2 FMAs, inverse column FFT. In-place on g_buf.
// ---------------------------------------------------------------------------
__global__ void __launch_bounds__(256) k_colfft_mlp(
        const float* __restrict__ w1g, const float* __restrict__ b1g,
        const float* __restrict__ w2g, const float* __restrict__ b2g){
    extern __shared__ char smraw[];
    float2*  T   = (float2*)smraw;                 // 4352 f2      [0, 34816)
    float2*  A   = (float2*)(smraw + 34816);       // 4112 f2      [34816, 67712)
    float2*  tw  = (float2*)(smraw + 67712);       // 256 f2       [67712, 69760)
    double2* w1p = (double2*)(smraw + 69760);      // 256 d2       [69760, 73856)
    double2* w2p = (double2*)(smraw + 73856);      // 256 d2       [73856, 77952)
    double*  b1p = (double*)(smraw + 77952);       // 16 d         [77952, 78080)
    double*  b2p = (double*)(smraw + 78080);       // 16 d         [78080, 78208)

    const int tid = threadIdx.x;
    const int f = tid >> 4, t = tid & 15;
    const int wf = blockIdx.x % WF;
    const int bk = blockIdx.x / WF;
    const int k = bk & 7, b = bk >> 3;

    build_tw(tw, tid);
    {   // weights: w1/w2 are [2][8][16][16] (i-major, o-minor), duplicate-packed
        float wr = w1g[k * 256 + tid], wi = w1g[2048 + k * 256 + tid];
        w1p[tid] = make_double2(pk(wr, wr), pk(wi, wi));
        wr = w2g[k * 256 + tid]; wi = w2g[2048 + k * 256 + tid];
        w2p[tid] = make_double2(pk(wr, wr), pk(wi, wi));
    }
    if (tid < 16){
        b1p[tid] = pk(b1g[k * 16 + tid], b1g[128 + k * 16 + tid]);
        b2p[tid] = pk(b2g[k * 16 + tid], b2g[128 + k * 16 + tid]);
    }

    float2* chp = g_buf + ((size_t)(b * CSZ + k * 16 + f) * WF + wf) * HDIM;

    float2 v[16];
#pragma unroll
    for (int n1 = 0; n1 < 16; n1++) v[n1] = chp[16 * n1 + t];
    dft16<false>(v);
    __syncthreads();                               // tw + weights ready
#pragma unroll
    for (int k1 = 0; k1 < 16; k1++){
        float2 bv = v[SLOT(k1)];
        if (k1) bv = cmul(bv, tw[t * k1]);
        T[f * 272 + k1 * 17 + t] = bv;
    }
    __syncthreads();
#pragma unroll
    for (int n2 = 0; n2 < 16; n2++) v[n2] = T[f * 272 + t * 17 + n2];
    dft16<false>(v);
#pragma unroll
    for (int k2 = 0; k2 < 16; k2++)
        A[f * 257 + t + 16 * k2] = v[SLOT(k2)];
    __syncthreads();

    // ---- MLP: one thread per h-bin, packed f32x2 complex GEMV ----
    {
        double xp[16];
#pragma unroll
        for (int i = 0; i < 16; i++){
            float2 q = A[i * 257 + tid];
            xp[i] = pk(q.x, q.y);
        }
        double o1p[16];
#pragma unroll
        for (int o = 0; o < 16; o++){
            double Aa = b1p[o], Bb = 0.;   // 0.0 == packed (0.f, 0.f)
#pragma unroll
            for (int i = 0; i < 16; i++){
                double2 w = w1p[i * 16 + o];
                Aa = ffma2(xp[i], w.x, Aa);
                Bb = ffma2(xp[i], w.y, Bb);
            }
            float alo, ahi, blo, bhi;
            upk(Aa, alo, ahi); upk(Bb, blo, bhi);
            o1p[o] = pk(fmaxf(alo - bhi, 0.f), fmaxf(ahi + blo, 0.f));
        }
#pragma unroll
        for (int o = 0; o < 16; o++){
            double Aa = b2p[o], Bb = 0.;
#pragma unroll
            for (int i = 0; i < 16; i++){
                double2 w = w2p[i * 16 + o];
                Aa = ffma2(o1p[i], w.x, Aa);
                Bb = ffma2(o1p[i], w.y, Bb);
            }
            float alo, ahi, blo, bhi;
            upk(Aa, alo, ahi); upk(Bb, blo, bhi);
            const float ar = alo - bhi, ai = ahi + blo;
            const float sr = copysignf(fmaxf(fabsf(ar) - 0.01f, 0.f), ar);
            const float si = copysignf(fmaxf(fabsf(ai) - 0.01f, 0.f), ai);
            float xr, xi; upk(xp[o], xr, xi);
            A[o * 257 + tid] = make_float2(sr * xr - si * xi,
                                           sr * xi + si * xr);
        }
    }
    __syncthreads();

    // ---- inverse column FFT (bin-strided in, coalesced time-domain out) ----
#pragma unroll
    for (int k2 = 0; k2 < 16; k2++) v[k2] = A[f * 257 + t + 16 * k2];
    dft16<true>(v);
#pragma unroll
    for (int m2 = 0; m2 < 16; m2++){
        float2 q = v[SLOT(m2)];
        if (m2) q = cmulc(q, tw[m2 * t]);
        T[f * 272 + m2 * 17 + t] = q;
    }
    __syncthreads();
#pragma unroll
    for (int n = 0; n < 16; n++) v[n] = T[f * 272 + t * 17 + n];
    dft16<true>(v);
#pragma unroll
    for (int m1 = 0; m1 < 16; m1++)
        chp[16 * m1 + t] = v[SLOT(m1)];
}

// ---------------------------------------------------------------------------
// K3: row irfft. CTA = 32 rows of one (b,c) image, 2 rows packed per inverse
// complex FFT. Hermitian extension + edge-bin imag zeroing == irfft semantics.
// Scale 1/256, add residual.
// ---------------------------------------------------------------------------
__global__ void __launch_bounds__(256) k_rowifft(const float* __restrict__ x,
                                                 float* __restrict__ out){
    extern __shared__ char smraw[];
    float2* sbuf = (float2*)smraw;                 // 4352 f2
    float2* tw   = (float2*)(smraw + 34816);       // 256 f2

    const int tid = threadIdx.x;
    const int f = tid >> 4, t = tid & 15;
    const int bc = blockIdx.x >> 3;
    const int h0 = (blockIdx.x & 7) << 5;

    build_tw(tw, tid);

    const float2* gsrc = g_buf + (size_t)bc * WF * HDIM;
    // Build packed full spectrum Z[f][0..255], Z = X0 + i*X1
    for (int e = tid; e < WF * 16; e += 256){
        const int wf = e >> 4, fp = e & 15;
        float4 q = *(const float4*)(gsrc + (size_t)wf * HDIM + h0 + 2 * fp);
        float ay = q.y, by = q.w;
        if (wf == 0 || wf == 128){ ay = 0.f; by = 0.f; }   // irfft ignores edge imag
        sbuf[fp * 257 + wf] = make_float2(q.x - by, ay + q.z);
        if (wf >= 1 && wf <= 127)
            sbuf[fp * 257 + 256 - wf] = make_float2(q.x + by, q.z - ay);
    }
    __syncthreads();

    float2 v[16];
#pragma unroll
    for (int k2 = 0; k2 < 16; k2++) v[k2] = sbuf[f * 257 + t + 16 * k2];
    __syncthreads();                               // S reads done before T writes
    dft16<true>(v);
#pragma unroll
    for (int m2 = 0; m2 < 16; m2++){
        float2 q = v[SLOT(m2)];
        if (m2) q = cmulc(q, tw[m2 * t]);
        sbuf[f * 272 + m2 * 17 + t] = q;
    }
    __syncthreads();
#pragma unroll
    for (int n = 0; n < 16; n++) v[n] = sbuf[f * 272 + t * 17 + n];
    dft16<true>(v);

    const float* bias0 = x   + ((size_t)bc * HDIM + h0 + 2 * f) * WDIM;
    float*       o0    = out + ((size_t)bc * HDIM + h0 + 2 * f) * WDIM;
#pragma unroll
    for (int m1 = 0; m1 < 16; m1++){
        float2 z = v[SLOT(m1)];
        const int w_ = 16 * m1 + t;
        o0[w_]        = z.x * (1.f / 256.f) + bias0[w_];
        o0[WDIM + w_] = z.y * (1.f / 256.f) + bias0[WDIM + w_];
    }
}

extern "C" void kernel_launch(void* const* d_in, const int* in_sizes, int n_in,
                              void* d_out, int out_size) {
    const float* x  = (const float*)d_in[0];
    const float* w1 = (const float*)d_in[1];
    const float* b1 = (const float*)d_in[2];
    const float* w2 = (const float*)d_in[3];
    const float* b2 = (const float*)d_in[4];
    float* out = (float*)d_out;

    const int SMEM_ROW = 34816 + 2048;             // 36864
    const int SMEM_COL = 78208;

    cudaFuncSetAttribute(k_rowfft,     cudaFuncAttributeMaxDynamicSharedMemorySize, SMEM_ROW);
    cudaFuncSetAttribute(k_colfft_mlp, cudaFuncAttributeMaxDynamicSharedMemorySize, SMEM_COL);
    cudaFuncSetAttribute(k_rowifft,    cudaFuncAttributeMaxDynamicSharedMemorySize, SMEM_ROW);

    k_rowfft<<<BSZ * CSZ * (HDIM / 32), 256, SMEM_ROW>>>(x);
    k_colfft_mlp<<<BSZ * NBLK * WF, 256, SMEM_COL>>>(w1, b1, w2, b2);
    k_rowifft<<<BSZ * CSZ * (HDIM / 32), 256, SMEM_ROW>>>(x, out);
}